// round 8
// baseline (speedup 1.0000x reference)
#include <cuda_runtime.h>

// Problem constants
#define DIMN   16
#define SECN   16
#define SUBN   16
#define EN     256
#define BATCHN 128
#define SLN    64

// Output layout (flattened reference tuple, float32)
#define OFF_TZ1  0
#define OFF_TZ2  1024
#define OFF_FWD  2048
#define OFF_EQ   18432
#define OFF_ATT  18433
#define OFF_ORTH 35841
#define OFF_PAR  35842
#define OFF_COM  35843
#define OFF_SPA  35844
#define OFF_SEC  35845
#define OFF_SUB  35846

#define NBACK 2424   // k_back grid size

// Scratch
__device__ __align__(16) float  g_syms[EN * 256];        // expm(ge)
__device__ __align__(16) float  g_u[EN * BATCHN * DIMN]; // normalized diff rows
__device__ __align__(16) float  g_w[SLN * EN];           // switch*fprob weights
__device__ __align__(16) float  g_S[SLN * 256];          // S matrices
__device__ __align__(16) float  g_inv[SLN * 256];        // expm(-S)
__device__ double g_acc[8] = {0};     // 0 sparse 1 parallel 2 orth 3 commut 4 sector
__device__ unsigned g_done = 0;       // k_back completion counter

// ---------------------------------------------------------------------------
// f32x2 packed helpers
__device__ __forceinline__ unsigned long long pk2(float lo, float hi) {
    unsigned long long r;
    asm("mov.b64 %0, {%1, %2};" : "=l"(r) : "f"(lo), "f"(hi));
    return r;
}
__device__ __forceinline__ void upk2(float& lo, float& hi, unsigned long long v) {
    asm("mov.b64 {%0, %1}, %2;" : "=f"(lo), "=f"(hi) : "l"(v));
}
__device__ __forceinline__ unsigned long long ffma2(unsigned long long a,
                                                    unsigned long long b,
                                                    unsigned long long c) {
    unsigned long long d;
    asm("fma.rn.f32x2 %0, %1, %2, %3;" : "=l"(d) : "l"(a), "l"(b), "l"(c));
    return d;
}

// ---------------------------------------------------------------------------
// expm of one 16x16 matrix per block (256 threads): scaling & squaring +
// order-12 Taylor Horner, ping-pong buffers, 2-way split dot chains.
// sm must hold >= 784 floats.
__device__ __forceinline__ void expm_body(const float* __restrict__ src,
                                          float* __restrict__ dst, float sign,
                                          float* sm) {
    float* Bm  = sm;
    float* Pa  = sm + 256;
    float* Pb  = sm + 512;
    float* red = sm + 768;   // 16
    __shared__ int s_sh;
    const int tid = threadIdx.x;
    const int r = tid >> 4, c = tid & 15;

    float a = sign * src[tid];

    Pb[tid] = fabsf(a);
    __syncthreads();
    if (tid < 16) {
        float rs = 0.f;
        #pragma unroll
        for (int k = 0; k < 16; k++) rs += Pb[tid * 16 + k];
        red[tid] = rs;
    }
    __syncthreads();
    if (tid == 0) {
        float mx = 0.f;
        #pragma unroll
        for (int k = 0; k < 16; k++) mx = fmaxf(mx, red[k]);
        int s = 0;
        while (mx > 0.25f && s < 48) { mx *= 0.5f; s++; }
        s_sh = s;
    }
    __syncthreads();
    const int s = s_sh;

    float b = a * exp2f(-(float)s);
    Bm[tid] = b;
    const float eye = (r == c) ? 1.0f : 0.0f;
    float res = b * (1.0f / 12.0f) + eye;
    Pa[tid] = res;

    float* cur = Pa;
    float* nxt = Pb;
    for (int k = 11; k >= 1; k--) {
        __syncthreads();
        float a0 = 0.f, a1 = 0.f;
        #pragma unroll
        for (int j = 0; j < 16; j += 2) {
            a0 += Bm[r * 16 + j] * cur[j * 16 + c];
            a1 += Bm[r * 16 + j + 1] * cur[(j + 1) * 16 + c];
        }
        res = (a0 + a1) * (1.0f / (float)k) + eye;
        nxt[tid] = res;
        float* t_ = cur; cur = nxt; nxt = t_;
    }
    for (int i = 0; i < s; i++) {
        __syncthreads();
        float a0 = 0.f, a1 = 0.f;
        #pragma unroll
        for (int j = 0; j < 16; j += 2) {
            a0 += cur[r * 16 + j] * cur[j * 16 + c];
            a1 += cur[r * 16 + j + 1] * cur[(j + 1) * 16 + c];
        }
        res = a0 + a1;
        nxt[tid] = res;
        float* t_ = cur; cur = nxt; nxt = t_;
    }
    dst[tid] = res;
}

// ---------------------------------------------------------------------------
// K1: blocks [0,256) expm(ge); [256,376) commut pairs; [376,440) head rows.
__global__ void __launch_bounds__(256) k_front(
        const float* __restrict__ ge,
        const float* __restrict__ mean, const float* __restrict__ logvar,
        const float* __restrict__ z, const float* __restrict__ lw,
        const float* __restrict__ lb, const float* __restrict__ gn,
        float* __restrict__ out) {
    __shared__ float sm[1300];
    const int tid = threadIdx.x;
    const int blk = blockIdx.x;

    if (blk < 256) {
        expm_body(ge + blk * 256, g_syms + blk * 256, 1.0f, sm);
    } else if (blk < 376) {
        // ---- commut pair j = blk-256 ----
        float* gA  = sm;
        float* gB  = sm + 256;
        float* gCa = sm + 512;
        float* gCb = sm + 768;
        float* rwp = sm + 1024;
        const int j = blk - 256;
        int p = j;
        int a = 0;
        while (p >= 15 - a) { p -= 15 - a; a++; }
        const int b2 = a + 1 + p;
        const int r = tid >> 4, s = tid & 15;

        gA[tid] = ge[a * 256 + tid];
        gB[tid] = ge[b2 * 256 + tid];
        {
            int c = tid >> 4, ss = tid & 15;
            gCa[tid] = ge[(c * 16) * 256 + a * 16 + ss];
            gCb[tid] = ge[(c * 16) * 256 + b2 * 16 + ss];
        }
        __syncthreads();

        float R1 = 0.f, R2 = 0.f;
        #pragma unroll
        for (int cc = 0; cc < 16; cc++) {
            R1 += gA[r * 16 + cc] * gCb[cc * 16 + s];
            R2 += gB[r * 16 + cc] * gCa[cc * 16 + s];
        }
        float d = R1 - R2;
        float local = d * d;
        #pragma unroll
        for (int off = 16; off > 0; off >>= 1)
            local += __shfl_down_sync(0xffffffffu, local, off);
        if ((tid & 31) == 0) rwp[tid >> 5] = local;
        __syncthreads();
        if (tid == 0) {
            float t = 0.f;
            #pragma unroll
            for (int w = 0; w < 8; w++) t += rwp[w];
            atomicAdd(&g_acc[3], (double)(2.0f * t) * (double)(120 - j));
        }
    } else {
        // ---- head row b = blk-376 ----
        float* feat = sm;          // 64
        float* prob = sm + 64;     // 288
        float* sw   = sm + 352;    // 16
        const int b = blk - 376;
        const int t = tid;

        if (t < 64) {
            float v;
            if (t < 16)       v = mean[b * 16 + t];
            else if (t < 32)  v = expf(0.5f * logvar[b * 16 + (t - 16)]);
            else if (t < 48)  v = mean[(64 + b) * 16 + (t - 32)];
            else              v = expf(0.5f * mean[(64 + b) * 16 + (t - 48)]);
            feat[t] = v;
        }
        __syncthreads();

        // warp-per-row GEMV: coalesced lw reads + shfl reduction
        {
            const int w = t >> 5, lane = t & 31;
            const float f0 = feat[lane], f1 = feat[lane + 32];
            for (int jj = w; jj < 288; jj += 8) {
                const float* wrow = lw + jj * 64;
                float acc = wrow[lane] * f0 + wrow[lane + 32] * f1;
                acc += __shfl_down_sync(0xffffffffu, acc, 16);
                acc += __shfl_down_sync(0xffffffffu, acc, 8);
                acc += __shfl_down_sync(0xffffffffu, acc, 4);
                acc += __shfl_down_sync(0xffffffffu, acc, 2);
                acc += __shfl_down_sync(0xffffffffu, acc, 1);
                if (lane == 0) prob[jj] = acc + lb[jj];
            }
        }
        __syncthreads();

        if (t < 16) {
            const int s = t;
            float l0 = prob[2 * s], l1 = prob[2 * s + 1];
            float m = fmaxf(l0, l1);
            float e0 = expf(l0 - m), e1 = expf(l1 - m);
            float Z = e0 + e1;
            float p0 = e0 / Z, p1 = e1 / Z;
            float mm = fmaxf(p0, p1);
            float lse = mm + logf(expf(p0 - mm) + expf(p1 - mm));
            float zd = z[b * 16 + s] - z[(64 + b) * 16 + s];
            int tgt = (fabsf(zd) > 0.2f) ? 1 : 0;
            float v = -((tgt ? p1 : p0) - lse);
            v += __shfl_down_sync(0x0000ffffu, v, 8);
            v += __shfl_down_sync(0x0000ffffu, v, 4);
            v += __shfl_down_sync(0x0000ffffu, v, 2);
            v += __shfl_down_sync(0x0000ffffu, v, 1);
            if (s == 0) atomicAdd(&g_acc[4], (double)v);

            float g0 = gn[(b * 16 + s) * 2], g1 = gn[(b * 16 + s) * 2 + 1];
            const float TAUF = 0.0001f;
            float d0 = (l0 + g0) / TAUF, d1 = (l1 + g1) / TAUF;
            float m2 = fmaxf(d0, d1);
            float a0 = expf(d0 - m2), a1 = expf(d1 - m2);
            float attn1 = a1 / (a0 + a1);
            sw[s] = attn1;
            out[OFF_ATT + b * 272 + s] = attn1;
        }
        __syncthreads();

        if (t < 16) {
            const int s = t;
            float mx = -1e30f;
            #pragma unroll
            for (int u = 0; u < 16; u++) mx = fmaxf(mx, prob[32 + s * 16 + u]);
            float ex[16];
            float sum = 0.f;
            #pragma unroll
            for (int u = 0; u < 16; u++) {
                ex[u] = expf(prob[32 + s * 16 + u] - mx);
                sum += ex[u];
            }
            float inv = 1.0f / sum;
            float swv = sw[s];
            #pragma unroll
            for (int u = 0; u < 16; u++) {
                float f = ex[u] * inv;
                out[OFF_ATT + b * 272 + 16 + s * 16 + u] = f;
                g_w[b * 256 + s * 16 + u] = f * swv;
            }
        }
    }
}

// ---------------------------------------------------------------------------
// K2: blocks [0,128) diff (2 group-elements per block); [128,192) subsyms.
__global__ void __launch_bounds__(256) k_mid(const float* __restrict__ z,
                                             const float* __restrict__ ge,
                                             float* __restrict__ out) {
    __shared__ float sm[2816];
    const int tid = threadIdx.x;
    const int blk = blockIdx.x;

    if (blk < 128) {
        float* sy  = sm;          // 512 (two 16x16)
        float* zsh = sm + 512;    // 2048
        float* rwp = sm + 2560;   // 8

        sy[tid] = g_syms[blk * 512 + tid];
        sy[tid + 256] = g_syms[blk * 512 + 256 + tid];
        #pragma unroll
        for (int i = 0; i < 8; i++) zsh[tid + 256 * i] = z[tid + 256 * i];
        __syncthreads();

        const int half = tid >> 7, b = tid & 127;
        const float* syp = sy + half * 256;
        float zr[16];
        #pragma unroll
        for (int d = 0; d < 16; d++) zr[d] = zsh[b * 16 + d];

        float dv[16];
        float s2 = 0.f, mx = 0.f;
        #pragma unroll
        for (int d = 0; d < 16; d++) {
            float dot0 = 0.f, dot1 = 0.f;
            #pragma unroll
            for (int k = 0; k < 16; k += 2) {
                dot0 += zr[k] * syp[k * 16 + d];
                dot1 += zr[k + 1] * syp[(k + 1) * 16 + d];
            }
            float v = zr[d] - (dot0 + dot1);
            dv[d] = v;
            float q = v * v;
            s2 += q;
            mx = fmaxf(mx, q);
        }
        float sp = s2 - mx;
        sp = sp * sp;

        #pragma unroll
        for (int off = 16; off > 0; off >>= 1)
            sp += __shfl_down_sync(0xffffffffu, sp, off);
        if ((tid & 31) == 0) rwp[tid >> 5] = sp;
        __syncthreads();
        if (tid == 0) {
            float t = 0.f;
            #pragma unroll
            for (int w = 0; w < 8; w++) t += rwp[w];
            atomicAdd(&g_acc[0], (double)t);
        }

        const float inv = rsqrtf(s2);
        float* dstu = g_u + ((blk * 2 + half) * 128 + b) * 16;
        #pragma unroll
        for (int d = 0; d < 16; d++) dstu[d] = dv[d] * inv;
    } else {
        // ---- subsyms b = blk-128 ----
        float* wsh = sm;
        const int b = blk - 128;
        wsh[tid] = g_w[b * 256 + tid];
        __syncthreads();

        float Sacc = 0.f;
        #pragma unroll 1
        for (int s = 0; s < 16; s++) {
            float a = 0.f;
            #pragma unroll
            for (int u = 0; u < 16; u++)
                a += wsh[s * 16 + u] * ge[(s * 16 + u) * 256 + tid];
            out[OFF_SUB + b * 4096 + s * 256 + tid] = a;
            Sacc += a;
        }
        g_S[b * 256 + tid] = Sacc;
    }
}

// ---------------------------------------------------------------------------
// K3: blocks [0,128) expm(+/-S); blocks [128,2424) gram tiles.
// Last-to-finish block runs the tail (tz + equivariant + finalize + resets).
__global__ void __launch_bounds__(256) k_back(const int* __restrict__ sidx,
                                              const float* __restrict__ z,
                                              float* __restrict__ out) {
    __shared__ float sm[4352];
    __shared__ unsigned last_sh;
    const int tid = threadIdx.x;

    if (blockIdx.x < 128) {
        const int b = blockIdx.x & 63;
        const bool inv = blockIdx.x >= 64;
        float* dst = inv ? (g_inv + b * 256) : (out + OFF_FWD + b * 256);
        expm_body(g_S + b * 256, dst, inv ? -1.0f : 1.0f, sm);
    } else {
        float* As  = sm;
        float* Bs  = sm + 2048;
        float* rwp = sm + 4096;
        const int bi = blockIdx.x - 128;
        const bool isOrth = bi >= 2176;

        const float* baseA;
        const float* baseB;
        float mult;
        if (!isOrth) {
            const int sec = bi / 136;
            int p = bi % 136;
            int ti = 0;
            while (p >= 16 - ti) { p -= 16 - ti; ti++; }
            const int tj = ti + p;
            baseA = g_u + (sec * 2048 + ti * 128) * 16;
            baseB = g_u + (sec * 2048 + tj * 128) * 16;
            mult = (ti == tj) ? 1.0f : 2.0f;
        } else {
            int p = bi - 2176;
            int s = 0;
            while (p >= 15 - s) { p -= 15 - s; s++; }
            const int t2 = s + 1 + p;
            baseA = g_u + (s * 16 + sidx[s]) * 2048;
            baseB = g_u + (t2 * 16 + sidx[t2]) * 2048;
            mult = 2.0f;
        }

        // Load both 128x16 tiles transposed to [k][m].
        {
            const float4* a4 = (const float4*)baseA;
            const float4* b4 = (const float4*)baseB;
            #pragma unroll
            for (int i = 0; i < 2; i++) {
                const int idx = tid * 2 + i;
                const float4 va = a4[idx];
                const float4 vb = b4[idx];
                const int m = idx >> 2;
                const int k = (idx & 3) * 4;
                As[(k + 0) * 128 + m] = va.x; As[(k + 1) * 128 + m] = va.y;
                As[(k + 2) * 128 + m] = va.z; As[(k + 3) * 128 + m] = va.w;
                Bs[(k + 0) * 128 + m] = vb.x; Bs[(k + 1) * 128 + m] = vb.y;
                Bs[(k + 2) * 128 + m] = vb.z; Bs[(k + 3) * 128 + m] = vb.w;
            }
        }
        __syncthreads();

        const int tx = tid & 15, ty = tid >> 4;
        unsigned long long acc[8][4];
        #pragma unroll
        for (int m = 0; m < 8; m++)
            #pragma unroll
            for (int n = 0; n < 4; n++) acc[m][n] = 0ULL;

        #pragma unroll
        for (int k = 0; k < 16; k++) {
            const float4 a0 = *(const float4*)(As + k * 128 + ty * 8);
            const float4 a1 = *(const float4*)(As + k * 128 + ty * 8 + 4);
            unsigned long long bp[4];
            {
                const ulonglong2 q0 = *(const ulonglong2*)(Bs + k * 128 + tx * 8);
                const ulonglong2 q1 = *(const ulonglong2*)(Bs + k * 128 + tx * 8 + 4);
                bp[0] = q0.x; bp[1] = q0.y; bp[2] = q1.x; bp[3] = q1.y;
            }
            const float av[8] = {a0.x, a0.y, a0.z, a0.w, a1.x, a1.y, a1.z, a1.w};
            #pragma unroll
            for (int m = 0; m < 8; m++) {
                const unsigned long long am = pk2(av[m], av[m]);
                #pragma unroll
                for (int n = 0; n < 4; n++) acc[m][n] = ffma2(am, bp[n], acc[m][n]);
            }
        }

        float local = 0.f;
        #pragma unroll
        for (int m = 0; m < 8; m++) {
            float l0, h0, l1, h1, l2, h2, l3, h3;
            upk2(l0, h0, acc[m][0]); upk2(l1, h1, acc[m][1]);
            upk2(l2, h2, acc[m][2]); upk2(l3, h3, acc[m][3]);
            if (isOrth) {
                local += l0 * l0 + h0 * h0 + l1 * l1 + h1 * h1
                       + l2 * l2 + h2 * h2 + l3 * l3 + h3 * h3;
            } else {
                // fuse 4 logs: factors >= 1e-9 so product >= 1e-36 > FLT_MIN
                float p0 = fmaf(l0, l0, 1e-9f) * fmaf(h0, h0, 1e-9f)
                         * fmaf(l1, l1, 1e-9f) * fmaf(h1, h1, 1e-9f);
                float p1 = fmaf(l2, l2, 1e-9f) * fmaf(h2, h2, 1e-9f)
                         * fmaf(l3, l3, 1e-9f) * fmaf(h3, h3, 1e-9f);
                local -= __logf(p0) + __logf(p1);
            }
        }
        local *= mult;

        #pragma unroll
        for (int off = 16; off > 0; off >>= 1)
            local += __shfl_down_sync(0xffffffffu, local, off);
        if ((tid & 31) == 0) rwp[tid >> 5] = local;
        __syncthreads();
        if (tid == 0) {
            float t = 0.f;
            #pragma unroll
            for (int w = 0; w < 8; w++) t += rwp[w];
            atomicAdd(&g_acc[isOrth ? 2 : 1], (double)t);
        }
    }

    // ---- completion counter; last block runs the tail ----
    __threadfence();
    __syncthreads();
    if (tid == 0) last_sh = (atomicAdd(&g_done, 1u) == NBACK - 1u) ? 1u : 0u;
    __syncthreads();
    if (!last_sh) return;
    __threadfence();

    // tz1/tz2 + equivariant with 256 threads: thread = (b, d-quad)
    {
        const int b = tid >> 2, q = tid & 3;
        const float4* f4 = (const float4*)(out + OFF_FWD);
        const float4* i4 = (const float4*)g_inv;
        float4 a1 = make_float4(0.f, 0.f, 0.f, 0.f);
        float4 a2 = make_float4(0.f, 0.f, 0.f, 0.f);
        #pragma unroll
        for (int k = 0; k < 16; k++) {
            const float z1 = z[b * 16 + k];
            const float z2 = z[(64 + b) * 16 + k];
            const float4 fv = f4[b * 64 + k * 4 + q];
            const float4 iv = i4[b * 64 + k * 4 + q];
            a1.x += z1 * fv.x; a1.y += z1 * fv.y; a1.z += z1 * fv.z; a1.w += z1 * fv.w;
            a2.x += z2 * iv.x; a2.y += z2 * iv.y; a2.z += z2 * iv.z; a2.w += z2 * iv.w;
        }
        ((float4*)(out + OFF_TZ1))[b * 4 + q] = a1;
        ((float4*)(out + OFF_TZ2))[b * 4 + q] = a2;

        const float4 za = ((const float4*)z)[b * 4 + q];
        const float4 zb = ((const float4*)z)[(64 + b) * 4 + q];
        float e = 0.f;
        float d;
        d = a2.x - za.x; e += d * d;  d = a2.y - za.y; e += d * d;
        d = a2.z - za.z; e += d * d;  d = a2.w - za.w; e += d * d;
        d = a1.x - zb.x; e += d * d;  d = a1.y - zb.y; e += d * d;
        d = a1.z - zb.z; e += d * d;  d = a1.w - zb.w; e += d * d;

        #pragma unroll
        for (int off = 16; off > 0; off >>= 1)
            e += __shfl_down_sync(0xffffffffu, e, off);
        if ((tid & 31) == 0) sm[tid >> 5] = e;
        __syncthreads();
        if (tid == 0) {
            float t = 0.f;
            #pragma unroll
            for (int w = 0; w < 8; w++) t += sm[w];
            out[OFF_EQ]   = t * (1.0f / 1024.0f);
            out[OFF_SPA]  = (float)(g_acc[0] / 32768.0);
            out[OFF_PAR]  = (float)(g_acc[1] / 67108864.0);
            out[OFF_ORTH] = (float)(g_acc[2] / 4194304.0);
            out[OFF_COM]  = (float)(g_acc[3] / 16777216.0);
            out[OFF_SEC]  = (float)(g_acc[4] / 64.0);
            #pragma unroll
            for (int i = 0; i < 8; i++) g_acc[i] = 0.0;   // ready for next replay
            g_done = 0;
        }
    }
}

// ---------------------------------------------------------------------------
extern "C" void kernel_launch(void* const* d_in, const int* in_sizes, int n_in,
                              void* d_out, int out_size) {
    const float* mean   = (const float*)d_in[0];
    const float* logvar = (const float*)d_in[1];
    const float* z      = (const float*)d_in[2];
    const float* ge     = (const float*)d_in[3];
    const float* lw     = (const float*)d_in[4];
    const float* lb     = (const float*)d_in[5];
    const float* gn     = (const float*)d_in[6];
    const int*   sidx   = (const int*)d_in[7];
    float* out = (float*)d_out;

    k_front<<<440, 256>>>(ge, mean, logvar, z, lw, lb, gn, out); // expm(ge)+commut+head
    k_mid<<<192, 256>>>(z, ge, out);                             // diff+sparse+subsyms
    k_back<<<NBACK, 256>>>(sidx, z, out);                        // expm(+/-S)+gram+tail
}

// round 9
// speedup vs baseline: 1.1422x; 1.1422x over previous
#include <cuda_runtime.h>

// Problem constants
#define DIMN   16
#define SECN   16
#define SUBN   16
#define EN     256
#define BATCHN 128
#define SLN    64

// Output layout (flattened reference tuple, float32)
#define OFF_TZ1  0
#define OFF_TZ2  1024
#define OFF_FWD  2048
#define OFF_EQ   18432
#define OFF_ATT  18433
#define OFF_ORTH 35841
#define OFF_PAR  35842
#define OFF_COM  35843
#define OFF_SPA  35844
#define OFF_SEC  35845
#define OFF_SUB  35846

// Scratch
__device__ __align__(16) float  g_syms[EN * 256];        // expm(ge)
__device__ __align__(16) float  g_u[EN * BATCHN * DIMN]; // normalized diff rows
__device__ __align__(16) float  g_w[SLN * EN];           // switch*fprob weights
__device__ __align__(16) float  g_S[SLN * 256];          // S matrices
__device__ __align__(16) float  g_inv[SLN * 256];        // expm(-S)
__device__ double g_acc[8] = {0};     // 0 sparse 1 parallel 2 orth 3 commut 4 sector

// ---------------------------------------------------------------------------
// f32x2 packed helpers
__device__ __forceinline__ unsigned long long pk2(float lo, float hi) {
    unsigned long long r;
    asm("mov.b64 %0, {%1, %2};" : "=l"(r) : "f"(lo), "f"(hi));
    return r;
}
__device__ __forceinline__ void upk2(float& lo, float& hi, unsigned long long v) {
    asm("mov.b64 {%0, %1}, %2;" : "=f"(lo), "=f"(hi) : "l"(v));
}
__device__ __forceinline__ unsigned long long ffma2(unsigned long long a,
                                                    unsigned long long b,
                                                    unsigned long long c) {
    unsigned long long d;
    asm("fma.rn.f32x2 %0, %1, %2, %3;" : "=l"(d) : "l"(a), "l"(b), "l"(c));
    return d;
}

// ---------------------------------------------------------------------------
// Warp-cooperative expm of one 16x16 matrix: scaling & squaring + order-8
// Taylor Horner (theta=0.7, remainder ~1e-7). Lane owns half a row:
// r = lane>>1, cols [c0, c0+8), c0 = (lane&1)*8. A-row held in registers
// (partner half via shfl_xor 1); B columns read from smem (warp-broadcast).
// bufA/bufB: 256 floats each, per-warp.
__device__ __forceinline__ void warp_expm(const float* __restrict__ src,
                                          float* __restrict__ dst, float sign,
                                          float* bufA, float* bufB) {
    const int lane = threadIdx.x & 31;
    const int r = lane >> 1;
    const int c0 = (lane & 1) * 8;
    const int c0p = 8 - c0;
    const int base = lane * 8;            // == r*16 + c0

    float4 v0 = ((const float4*)src)[lane * 2];
    float4 v1 = ((const float4*)src)[lane * 2 + 1];
    float a[8] = {v0.x, v0.y, v0.z, v0.w, v1.x, v1.y, v1.z, v1.w};
    if (sign < 0.f) {
        #pragma unroll
        for (int k = 0; k < 8; k++) a[k] = -a[k];
    }

    // inf-norm: row sums then warp max
    float rs = 0.f;
    #pragma unroll
    for (int k = 0; k < 8; k++) rs += fabsf(a[k]);
    rs += __shfl_xor_sync(0xffffffffu, rs, 1);
    float mx = rs;
    #pragma unroll
    for (int off = 2; off < 32; off <<= 1)
        mx = fmaxf(mx, __shfl_xor_sync(0xffffffffu, mx, off));
    int s = 0;
    while (mx > 0.7f && s < 48) { mx *= 0.5f; s++; }

    const float sc = exp2f(-(float)s);
    float b[8], barow[16], res[8];
    #pragma unroll
    for (int k = 0; k < 8; k++) b[k] = a[k] * sc;
    #pragma unroll
    for (int k = 0; k < 8; k++) {
        barow[c0 + k] = b[k];
        res[k] = b[k] * (1.0f / 8.0f) + ((r == c0 + k) ? 1.0f : 0.0f);
    }
    #pragma unroll
    for (int k = 0; k < 8; k++)
        barow[c0p + k] = __shfl_xor_sync(0xffffffffu, b[k], 1);

    float* cur = bufA;
    float* nxt = bufB;
    #pragma unroll
    for (int k = 0; k < 8; k++) cur[base + k] = res[k];
    __syncwarp();

    // Horner: P <- B*P/kk + I, kk = 7..1
    #pragma unroll 1
    for (int kk = 7; kk >= 1; kk--) {
        float acc0 = 0.f, acc1 = 0.f, acc2 = 0.f, acc3 = 0.f;
        float acc4 = 0.f, acc5 = 0.f, acc6 = 0.f, acc7 = 0.f;
        #pragma unroll
        for (int j = 0; j < 16; j++) {
            const float av = barow[j];
            const float4 q0 = *(const float4*)(cur + j * 16 + c0);
            const float4 q1 = *(const float4*)(cur + j * 16 + c0 + 4);
            acc0 += av * q0.x; acc1 += av * q0.y; acc2 += av * q0.z; acc3 += av * q0.w;
            acc4 += av * q1.x; acc5 += av * q1.y; acc6 += av * q1.z; acc7 += av * q1.w;
        }
        const float inv = 1.0f / (float)kk;
        res[0] = acc0 * inv + ((r == c0 + 0) ? 1.f : 0.f);
        res[1] = acc1 * inv + ((r == c0 + 1) ? 1.f : 0.f);
        res[2] = acc2 * inv + ((r == c0 + 2) ? 1.f : 0.f);
        res[3] = acc3 * inv + ((r == c0 + 3) ? 1.f : 0.f);
        res[4] = acc4 * inv + ((r == c0 + 4) ? 1.f : 0.f);
        res[5] = acc5 * inv + ((r == c0 + 5) ? 1.f : 0.f);
        res[6] = acc6 * inv + ((r == c0 + 6) ? 1.f : 0.f);
        res[7] = acc7 * inv + ((r == c0 + 7) ? 1.f : 0.f);
        #pragma unroll
        for (int k = 0; k < 8; k++) nxt[base + k] = res[k];
        __syncwarp();
        float* t_ = cur; cur = nxt; nxt = t_;
    }

    // Squarings: P <- P*P.  res registers mirror cur's content for this lane.
    #pragma unroll 1
    for (int i = 0; i < s; i++) {
        float arow[16];
        #pragma unroll
        for (int k = 0; k < 8; k++) {
            arow[c0 + k] = res[k];
            arow[c0p + k] = __shfl_xor_sync(0xffffffffu, res[k], 1);
        }
        float acc0 = 0.f, acc1 = 0.f, acc2 = 0.f, acc3 = 0.f;
        float acc4 = 0.f, acc5 = 0.f, acc6 = 0.f, acc7 = 0.f;
        #pragma unroll
        for (int j = 0; j < 16; j++) {
            const float av = arow[j];
            const float4 q0 = *(const float4*)(cur + j * 16 + c0);
            const float4 q1 = *(const float4*)(cur + j * 16 + c0 + 4);
            acc0 += av * q0.x; acc1 += av * q0.y; acc2 += av * q0.z; acc3 += av * q0.w;
            acc4 += av * q1.x; acc5 += av * q1.y; acc6 += av * q1.z; acc7 += av * q1.w;
        }
        res[0] = acc0; res[1] = acc1; res[2] = acc2; res[3] = acc3;
        res[4] = acc4; res[5] = acc5; res[6] = acc6; res[7] = acc7;
        #pragma unroll
        for (int k = 0; k < 8; k++) nxt[base + k] = res[k];
        __syncwarp();
        float* t_ = cur; cur = nxt; nxt = t_;
    }

    ((float4*)dst)[lane * 2]     = make_float4(res[0], res[1], res[2], res[3]);
    ((float4*)dst)[lane * 2 + 1] = make_float4(res[4], res[5], res[6], res[7]);
}

// ---------------------------------------------------------------------------
// K1: blocks [0,32) expm(ge) 8/block; [32,152) commut; [152,664) head (b,sp).
__global__ void __launch_bounds__(256) k_front(
        const float* __restrict__ ge,
        const float* __restrict__ mean, const float* __restrict__ logvar,
        const float* __restrict__ z, const float* __restrict__ lw,
        const float* __restrict__ lb, const float* __restrict__ gn,
        float* __restrict__ out) {
    __shared__ float sm[4096];
    const int tid = threadIdx.x;
    const int wid = tid >> 5;
    const int blk = blockIdx.x;

    if (blk < 32) {
        const int m = blk * 8 + wid;
        warp_expm(ge + m * 256, g_syms + m * 256, 1.0f,
                  sm + wid * 512, sm + wid * 512 + 256);
    } else if (blk < 152) {
        // ---- commut pair j = blk-32 ----
        float* gA  = sm;
        float* gB  = sm + 256;
        float* gCa = sm + 512;
        float* gCb = sm + 768;
        float* rwp = sm + 1024;
        const int j = blk - 32;
        int p = j;
        int a = 0;
        while (p >= 15 - a) { p -= 15 - a; a++; }
        const int b2 = a + 1 + p;
        const int r = tid >> 4, s = tid & 15;

        gA[tid] = ge[a * 256 + tid];
        gB[tid] = ge[b2 * 256 + tid];
        {
            int c = tid >> 4, ss = tid & 15;
            gCa[tid] = ge[(c * 16) * 256 + a * 16 + ss];
            gCb[tid] = ge[(c * 16) * 256 + b2 * 16 + ss];
        }
        __syncthreads();

        float R1 = 0.f, R2 = 0.f;
        #pragma unroll
        for (int cc = 0; cc < 16; cc++) {
            R1 += gA[r * 16 + cc] * gCb[cc * 16 + s];
            R2 += gB[r * 16 + cc] * gCa[cc * 16 + s];
        }
        float d = R1 - R2;
        float local = d * d;
        #pragma unroll
        for (int off = 16; off > 0; off >>= 1)
            local += __shfl_down_sync(0xffffffffu, local, off);
        if ((tid & 31) == 0) rwp[tid >> 5] = local;
        __syncthreads();
        if (tid == 0) {
            float t = 0.f;
            #pragma unroll
            for (int w = 0; w < 8; w++) t += rwp[w];
            atomicAdd(&g_acc[3], (double)(2.0f * t) * (double)(120 - j));
        }
    } else {
        // ---- head: block = (b, sector-pair sp) ----
        float* feat  = sm;          // 64
        float* probl = sm + 64;     // 36 local rows
        const int idx = blk - 152;
        const int b = idx >> 3, sp = idx & 7;

        if (tid < 64) {
            float v;
            if (tid < 16)       v = mean[b * 16 + tid];
            else if (tid < 32)  v = expf(0.5f * logvar[b * 16 + (tid - 16)]);
            else if (tid < 48)  v = mean[(64 + b) * 16 + (tid - 32)];
            else                v = expf(0.5f * mean[(64 + b) * 16 + (tid - 48)]);
            feat[tid] = v;
        }
        __syncthreads();

        // 36 rows: lr<4 -> sector logits rows 4sp+lr; else fprob rows 32+32sp+(lr-4)
        {
            const int lane = tid & 31;
            const float f0 = feat[lane], f1 = feat[lane + 32];
            for (int lr = wid; lr < 36; lr += 8) {
                const int jj = (lr < 4) ? (4 * sp + lr) : (32 + 32 * sp + (lr - 4));
                const float* wrow = lw + jj * 64;
                float acc = wrow[lane] * f0 + wrow[lane + 32] * f1;
                acc += __shfl_down_sync(0xffffffffu, acc, 16);
                acc += __shfl_down_sync(0xffffffffu, acc, 8);
                acc += __shfl_down_sync(0xffffffffu, acc, 4);
                acc += __shfl_down_sync(0xffffffffu, acc, 2);
                acc += __shfl_down_sync(0xffffffffu, acc, 1);
                if (lane == 0) probl[lr] = acc + lb[jj];
            }
        }
        __syncthreads();

        if (tid < 2) {
            const int t = tid;
            const int s = 2 * sp + t;
            float l0 = probl[2 * t], l1 = probl[2 * t + 1];
            float m = fmaxf(l0, l1);
            float e0 = expf(l0 - m), e1 = expf(l1 - m);
            float Z = e0 + e1;
            float p0 = e0 / Z, p1 = e1 / Z;
            float mm = fmaxf(p0, p1);
            float lse = mm + logf(expf(p0 - mm) + expf(p1 - mm));
            float zd = z[b * 16 + s] - z[(64 + b) * 16 + s];
            int tgt = (fabsf(zd) > 0.2f) ? 1 : 0;
            float v = -((tgt ? p1 : p0) - lse);
            v += __shfl_down_sync(0x3u, v, 1);
            if (t == 0) atomicAdd(&g_acc[4], (double)v);

            float g0 = gn[(b * 16 + s) * 2], g1 = gn[(b * 16 + s) * 2 + 1];
            const float TAUF = 0.0001f;
            float d0 = (l0 + g0) / TAUF, d1 = (l1 + g1) / TAUF;
            float m2 = fmaxf(d0, d1);
            float a0 = expf(d0 - m2), a1 = expf(d1 - m2);
            float attn1 = a1 / (a0 + a1);
            out[OFF_ATT + b * 272 + s] = attn1;

            float mx = -1e30f;
            #pragma unroll
            for (int u = 0; u < 16; u++) mx = fmaxf(mx, probl[4 + 16 * t + u]);
            float ex[16];
            float sum = 0.f;
            #pragma unroll
            for (int u = 0; u < 16; u++) {
                ex[u] = expf(probl[4 + 16 * t + u] - mx);
                sum += ex[u];
            }
            float inv = 1.0f / sum;
            #pragma unroll
            for (int u = 0; u < 16; u++) {
                float f = ex[u] * inv;
                out[OFF_ATT + b * 272 + 16 + s * 16 + u] = f;
                g_w[b * 256 + s * 16 + u] = f * attn1;
            }
        }
    }
}

// ---------------------------------------------------------------------------
// K2: blocks [0,128) diff (2 group-elements per block); [128,192) subsyms.
__global__ void __launch_bounds__(256) k_mid(const float* __restrict__ z,
                                             const float* __restrict__ ge,
                                             float* __restrict__ out) {
    __shared__ float sm[2816];
    const int tid = threadIdx.x;
    const int blk = blockIdx.x;

    if (blk < 128) {
        float* sy  = sm;          // 512 (two 16x16)
        float* zsh = sm + 512;    // 2048
        float* rwp = sm + 2560;   // 8

        sy[tid] = g_syms[blk * 512 + tid];
        sy[tid + 256] = g_syms[blk * 512 + 256 + tid];
        #pragma unroll
        for (int i = 0; i < 8; i++) zsh[tid + 256 * i] = z[tid + 256 * i];
        __syncthreads();

        const int half = tid >> 7, b = tid & 127;
        const float* syp = sy + half * 256;
        float zr[16];
        #pragma unroll
        for (int d = 0; d < 16; d++) zr[d] = zsh[b * 16 + d];

        float dv[16];
        float s2 = 0.f, mx = 0.f;
        #pragma unroll
        for (int d = 0; d < 16; d++) {
            float dot0 = 0.f, dot1 = 0.f;
            #pragma unroll
            for (int k = 0; k < 16; k += 2) {
                dot0 += zr[k] * syp[k * 16 + d];
                dot1 += zr[k + 1] * syp[(k + 1) * 16 + d];
            }
            float v = zr[d] - (dot0 + dot1);
            dv[d] = v;
            float q = v * v;
            s2 += q;
            mx = fmaxf(mx, q);
        }
        float sp = s2 - mx;
        sp = sp * sp;

        #pragma unroll
        for (int off = 16; off > 0; off >>= 1)
            sp += __shfl_down_sync(0xffffffffu, sp, off);
        if ((tid & 31) == 0) rwp[tid >> 5] = sp;
        __syncthreads();
        if (tid == 0) {
            float t = 0.f;
            #pragma unroll
            for (int w = 0; w < 8; w++) t += rwp[w];
            atomicAdd(&g_acc[0], (double)t);
        }

        const float inv = rsqrtf(s2);
        float* dstu = g_u + ((blk * 2 + half) * 128 + b) * 16;
        #pragma unroll
        for (int d = 0; d < 16; d++) dstu[d] = dv[d] * inv;
    } else {
        // ---- subsyms b = blk-128 ----
        float* wsh = sm;
        const int b = blk - 128;
        wsh[tid] = g_w[b * 256 + tid];
        __syncthreads();

        float Sacc = 0.f;
        #pragma unroll 1
        for (int s = 0; s < 16; s++) {
            float a = 0.f;
            #pragma unroll
            for (int u = 0; u < 16; u++)
                a += wsh[s * 16 + u] * ge[(s * 16 + u) * 256 + tid];
            out[OFF_SUB + b * 4096 + s * 256 + tid] = a;
            Sacc += a;
        }
        g_S[b * 256 + tid] = Sacc;
    }
}

// ---------------------------------------------------------------------------
// K3: blocks [0,16) expm(+/-S) 8 matrices/block; blocks [16,2312) gram tiles.
__global__ void __launch_bounds__(256) k_back(const int* __restrict__ sidx,
                                              float* __restrict__ out) {
    __shared__ float sm[4352];
    const int tid = threadIdx.x;

    if (blockIdx.x < 16) {
        const int wid = tid >> 5;
        const int m = blockIdx.x * 8 + wid;     // 0..127
        const int b = m & 63;
        const bool inv = m >= 64;
        float* dst = inv ? (g_inv + b * 256) : (out + OFF_FWD + b * 256);
        warp_expm(g_S + b * 256, dst, inv ? -1.0f : 1.0f,
                  sm + wid * 512, sm + wid * 512 + 256);
        return;
    }

    float* As  = sm;
    float* Bs  = sm + 2048;
    float* rwp = sm + 4096;
    const int bi = blockIdx.x - 16;
    const bool isOrth = bi >= 2176;

    const float* baseA;
    const float* baseB;
    float mult;
    if (!isOrth) {
        const int sec = bi / 136;
        int p = bi % 136;
        int ti = 0;
        while (p >= 16 - ti) { p -= 16 - ti; ti++; }
        const int tj = ti + p;
        baseA = g_u + (sec * 2048 + ti * 128) * 16;
        baseB = g_u + (sec * 2048 + tj * 128) * 16;
        mult = (ti == tj) ? 1.0f : 2.0f;
    } else {
        int p = bi - 2176;
        int s = 0;
        while (p >= 15 - s) { p -= 15 - s; s++; }
        const int t2 = s + 1 + p;
        baseA = g_u + (s * 16 + sidx[s]) * 2048;
        baseB = g_u + (t2 * 16 + sidx[t2]) * 2048;
        mult = 2.0f;
    }

    // Load both 128x16 tiles transposed to [k][m].
    {
        const float4* a4 = (const float4*)baseA;
        const float4* b4 = (const float4*)baseB;
        #pragma unroll
        for (int i = 0; i < 2; i++) {
            const int idx = tid * 2 + i;
            const float4 va = a4[idx];
            const float4 vb = b4[idx];
            const int m = idx >> 2;
            const int k = (idx & 3) * 4;
            As[(k + 0) * 128 + m] = va.x; As[(k + 1) * 128 + m] = va.y;
            As[(k + 2) * 128 + m] = va.z; As[(k + 3) * 128 + m] = va.w;
            Bs[(k + 0) * 128 + m] = vb.x; Bs[(k + 1) * 128 + m] = vb.y;
            Bs[(k + 2) * 128 + m] = vb.z; Bs[(k + 3) * 128 + m] = vb.w;
        }
    }
    __syncthreads();

    const int tx = tid & 15, ty = tid >> 4;
    unsigned long long acc[8][4];
    #pragma unroll
    for (int m = 0; m < 8; m++)
        #pragma unroll
        for (int n = 0; n < 4; n++) acc[m][n] = 0ULL;

    #pragma unroll
    for (int k = 0; k < 16; k++) {
        const float4 a0 = *(const float4*)(As + k * 128 + ty * 8);
        const float4 a1 = *(const float4*)(As + k * 128 + ty * 8 + 4);
        unsigned long long bp[4];
        {
            const ulonglong2 q0 = *(const ulonglong2*)(Bs + k * 128 + tx * 8);
            const ulonglong2 q1 = *(const ulonglong2*)(Bs + k * 128 + tx * 8 + 4);
            bp[0] = q0.x; bp[1] = q0.y; bp[2] = q1.x; bp[3] = q1.y;
        }
        const float av[8] = {a0.x, a0.y, a0.z, a0.w, a1.x, a1.y, a1.z, a1.w};
        #pragma unroll
        for (int m = 0; m < 8; m++) {
            const unsigned long long am = pk2(av[m], av[m]);
            #pragma unroll
            for (int n = 0; n < 4; n++) acc[m][n] = ffma2(am, bp[n], acc[m][n]);
        }
    }

    float local = 0.f;
    #pragma unroll
    for (int m = 0; m < 8; m++) {
        float l0, h0, l1, h1, l2, h2, l3, h3;
        upk2(l0, h0, acc[m][0]); upk2(l1, h1, acc[m][1]);
        upk2(l2, h2, acc[m][2]); upk2(l3, h3, acc[m][3]);
        if (isOrth) {
            local += l0 * l0 + h0 * h0 + l1 * l1 + h1 * h1
                   + l2 * l2 + h2 * h2 + l3 * l3 + h3 * h3;
        } else {
            // fuse 4 logs: factors >= 1e-9 so product >= 1e-36 > FLT_MIN
            float p0 = fmaf(l0, l0, 1e-9f) * fmaf(h0, h0, 1e-9f)
                     * fmaf(l1, l1, 1e-9f) * fmaf(h1, h1, 1e-9f);
            float p1 = fmaf(l2, l2, 1e-9f) * fmaf(h2, h2, 1e-9f)
                     * fmaf(l3, l3, 1e-9f) * fmaf(h3, h3, 1e-9f);
            local -= __logf(p0) + __logf(p1);
        }
    }
    local *= mult;

    #pragma unroll
    for (int off = 16; off > 0; off >>= 1)
        local += __shfl_down_sync(0xffffffffu, local, off);
    if ((tid & 31) == 0) rwp[tid >> 5] = local;
    __syncthreads();
    if (tid == 0) {
        float t = 0.f;
        #pragma unroll
        for (int w = 0; w < 8; w++) t += rwp[w];
        atomicAdd(&g_acc[isOrth ? 2 : 1], (double)t);
    }
}

// ---------------------------------------------------------------------------
// K4: tz1/tz2 + equivariant + finalize scalars + reset accumulators.
// 256 threads: thread = (b, d-quad), float4 loads throughout.
__global__ void k_tail(const float* __restrict__ z, float* __restrict__ out) {
    __shared__ float sm[8];
    const int tid = threadIdx.x;
    const int b = tid >> 2, q = tid & 3;
    const float4* f4 = (const float4*)(out + OFF_FWD);
    const float4* i4 = (const float4*)g_inv;

    float4 a1 = make_float4(0.f, 0.f, 0.f, 0.f);
    float4 a2 = make_float4(0.f, 0.f, 0.f, 0.f);
    #pragma unroll
    for (int k = 0; k < 16; k++) {
        const float z1 = z[b * 16 + k];
        const float z2 = z[(64 + b) * 16 + k];
        const float4 fv = f4[b * 64 + k * 4 + q];
        const float4 iv = i4[b * 64 + k * 4 + q];
        a1.x += z1 * fv.x; a1.y += z1 * fv.y; a1.z += z1 * fv.z; a1.w += z1 * fv.w;
        a2.x += z2 * iv.x; a2.y += z2 * iv.y; a2.z += z2 * iv.z; a2.w += z2 * iv.w;
    }
    ((float4*)(out + OFF_TZ1))[b * 4 + q] = a1;
    ((float4*)(out + OFF_TZ2))[b * 4 + q] = a2;

    const float4 za = ((const float4*)z)[b * 4 + q];
    const float4 zb = ((const float4*)z)[(64 + b) * 4 + q];
    float e = 0.f;
    float d;
    d = a2.x - za.x; e += d * d;  d = a2.y - za.y; e += d * d;
    d = a2.z - za.z; e += d * d;  d = a2.w - za.w; e += d * d;
    d = a1.x - zb.x; e += d * d;  d = a1.y - zb.y; e += d * d;
    d = a1.z - zb.z; e += d * d;  d = a1.w - zb.w; e += d * d;

    #pragma unroll
    for (int off = 16; off > 0; off >>= 1)
        e += __shfl_down_sync(0xffffffffu, e, off);
    if ((tid & 31) == 0) sm[tid >> 5] = e;
    __syncthreads();
    if (tid == 0) {
        float t = 0.f;
        #pragma unroll
        for (int w = 0; w < 8; w++) t += sm[w];
        out[OFF_EQ]   = t * (1.0f / 1024.0f);
        out[OFF_SPA]  = (float)(g_acc[0] / 32768.0);
        out[OFF_PAR]  = (float)(g_acc[1] / 67108864.0);
        out[OFF_ORTH] = (float)(g_acc[2] / 4194304.0);
        out[OFF_COM]  = (float)(g_acc[3] / 16777216.0);
        out[OFF_SEC]  = (float)(g_acc[4] / 64.0);
        #pragma unroll
        for (int i = 0; i < 8; i++) g_acc[i] = 0.0;   // ready for next replay
    }
}

// ---------------------------------------------------------------------------
extern "C" void kernel_launch(void* const* d_in, const int* in_sizes, int n_in,
                              void* d_out, int out_size) {
    const float* mean   = (const float*)d_in[0];
    const float* logvar = (const float*)d_in[1];
    const float* z      = (const float*)d_in[2];
    const float* ge     = (const float*)d_in[3];
    const float* lw     = (const float*)d_in[4];
    const float* lb     = (const float*)d_in[5];
    const float* gn     = (const float*)d_in[6];
    const int*   sidx   = (const int*)d_in[7];
    float* out = (float*)d_out;

    k_front<<<664, 256>>>(ge, mean, logvar, z, lw, lb, gn, out); // expm(ge)+commut+head
    k_mid<<<192, 256>>>(z, ge, out);                             // diff+sparse+subsyms
    k_back<<<2312, 256>>>(sidx, out);                            // expm(+/-S)+gram
    k_tail<<<1, 256>>>(z, out);                                  // tz+finalize+reset
}

// round 10
// speedup vs baseline: 1.2821x; 1.1224x over previous
#include <cuda_runtime.h>

// Problem constants
#define DIMN   16
#define SECN   16
#define SUBN   16
#define EN     256
#define BATCHN 128
#define SLN    64

// Output layout (flattened reference tuple, float32)
#define OFF_TZ1  0
#define OFF_TZ2  1024
#define OFF_FWD  2048
#define OFF_EQ   18432
#define OFF_ATT  18433
#define OFF_ORTH 35841
#define OFF_PAR  35842
#define OFF_COM  35843
#define OFF_SPA  35844
#define OFF_SEC  35845
#define OFF_SUB  35846

// Scratch
__device__ __align__(16) float  g_syms[EN * 256];        // expm(ge)
__device__ __align__(16) float  g_u[EN * BATCHN * DIMN]; // normalized diff rows
__device__ __align__(16) float  g_w[SLN * EN];           // switch*fprob weights
__device__ __align__(16) float  g_S[SLN * 256];          // S matrices
__device__ __align__(16) float  g_inv[SLN * 256];        // expm(-S)
__device__ double g_acc[8] = {0};  // 0 sparse 1 parallel 2 orth 3 commut 4 sector 5 equiv

// ---------------------------------------------------------------------------
// f32x2 packed helpers
__device__ __forceinline__ unsigned long long pk2(float lo, float hi) {
    unsigned long long r;
    asm("mov.b64 %0, {%1, %2};" : "=l"(r) : "f"(lo), "f"(hi));
    return r;
}
__device__ __forceinline__ void upk2(float& lo, float& hi, unsigned long long v) {
    asm("mov.b64 {%0, %1}, %2;" : "=f"(lo), "=f"(hi) : "l"(v));
}
__device__ __forceinline__ unsigned long long ffma2(unsigned long long a,
                                                    unsigned long long b,
                                                    unsigned long long c) {
    unsigned long long d;
    asm("fma.rn.f32x2 %0, %1, %2, %3;" : "=l"(d) : "l"(a), "l"(b), "l"(c));
    return d;
}

// ---------------------------------------------------------------------------
// Warp-cooperative expm of one 16x16 matrix: scaling & squaring + order-8
// Taylor Horner (theta=0.7). Lane owns half a row: r = lane>>1, cols
// [c0, c0+8), c0 = (lane&1)*8. Result left in res_out registers AND stored.
__device__ __forceinline__ void warp_expm(const float* __restrict__ src,
                                          float* __restrict__ dst, float sign,
                                          float* bufA, float* bufB,
                                          float res[8]) {
    const int lane = threadIdx.x & 31;
    const int r = lane >> 1;
    const int c0 = (lane & 1) * 8;
    const int c0p = 8 - c0;
    const int base = lane * 8;            // == r*16 + c0

    float4 v0 = ((const float4*)src)[lane * 2];
    float4 v1 = ((const float4*)src)[lane * 2 + 1];
    float a[8] = {v0.x, v0.y, v0.z, v0.w, v1.x, v1.y, v1.z, v1.w};
    if (sign < 0.f) {
        #pragma unroll
        for (int k = 0; k < 8; k++) a[k] = -a[k];
    }

    // inf-norm: row sums then warp max
    float rs = 0.f;
    #pragma unroll
    for (int k = 0; k < 8; k++) rs += fabsf(a[k]);
    rs += __shfl_xor_sync(0xffffffffu, rs, 1);
    float mx = rs;
    #pragma unroll
    for (int off = 2; off < 32; off <<= 1)
        mx = fmaxf(mx, __shfl_xor_sync(0xffffffffu, mx, off));
    int s = 0;
    while (mx > 0.7f && s < 48) { mx *= 0.5f; s++; }

    const float sc = exp2f(-(float)s);
    float b[8], barow[16];
    #pragma unroll
    for (int k = 0; k < 8; k++) b[k] = a[k] * sc;
    #pragma unroll
    for (int k = 0; k < 8; k++) {
        barow[c0 + k] = b[k];
        res[k] = b[k] * (1.0f / 8.0f) + ((r == c0 + k) ? 1.0f : 0.0f);
    }
    #pragma unroll
    for (int k = 0; k < 8; k++)
        barow[c0p + k] = __shfl_xor_sync(0xffffffffu, b[k], 1);

    float* cur = bufA;
    float* nxt = bufB;
    #pragma unroll
    for (int k = 0; k < 8; k++) cur[base + k] = res[k];
    __syncwarp();

    // Horner: P <- B*P/kk + I, kk = 7..1
    #pragma unroll 1
    for (int kk = 7; kk >= 1; kk--) {
        float acc0 = 0.f, acc1 = 0.f, acc2 = 0.f, acc3 = 0.f;
        float acc4 = 0.f, acc5 = 0.f, acc6 = 0.f, acc7 = 0.f;
        #pragma unroll
        for (int j = 0; j < 16; j++) {
            const float av = barow[j];
            const float4 q0 = *(const float4*)(cur + j * 16 + c0);
            const float4 q1 = *(const float4*)(cur + j * 16 + c0 + 4);
            acc0 += av * q0.x; acc1 += av * q0.y; acc2 += av * q0.z; acc3 += av * q0.w;
            acc4 += av * q1.x; acc5 += av * q1.y; acc6 += av * q1.z; acc7 += av * q1.w;
        }
        const float inv = 1.0f / (float)kk;
        res[0] = acc0 * inv + ((r == c0 + 0) ? 1.f : 0.f);
        res[1] = acc1 * inv + ((r == c0 + 1) ? 1.f : 0.f);
        res[2] = acc2 * inv + ((r == c0 + 2) ? 1.f : 0.f);
        res[3] = acc3 * inv + ((r == c0 + 3) ? 1.f : 0.f);
        res[4] = acc4 * inv + ((r == c0 + 4) ? 1.f : 0.f);
        res[5] = acc5 * inv + ((r == c0 + 5) ? 1.f : 0.f);
        res[6] = acc6 * inv + ((r == c0 + 6) ? 1.f : 0.f);
        res[7] = acc7 * inv + ((r == c0 + 7) ? 1.f : 0.f);
        #pragma unroll
        for (int k = 0; k < 8; k++) nxt[base + k] = res[k];
        __syncwarp();
        float* t_ = cur; cur = nxt; nxt = t_;
    }

    // Squarings: P <- P*P.
    #pragma unroll 1
    for (int i = 0; i < s; i++) {
        float arow[16];
        #pragma unroll
        for (int k = 0; k < 8; k++) {
            arow[c0 + k] = res[k];
            arow[c0p + k] = __shfl_xor_sync(0xffffffffu, res[k], 1);
        }
        float acc0 = 0.f, acc1 = 0.f, acc2 = 0.f, acc3 = 0.f;
        float acc4 = 0.f, acc5 = 0.f, acc6 = 0.f, acc7 = 0.f;
        #pragma unroll
        for (int j = 0; j < 16; j++) {
            const float av = arow[j];
            const float4 q0 = *(const float4*)(cur + j * 16 + c0);
            const float4 q1 = *(const float4*)(cur + j * 16 + c0 + 4);
            acc0 += av * q0.x; acc1 += av * q0.y; acc2 += av * q0.z; acc3 += av * q0.w;
            acc4 += av * q1.x; acc5 += av * q1.y; acc6 += av * q1.z; acc7 += av * q1.w;
        }
        res[0] = acc0; res[1] = acc1; res[2] = acc2; res[3] = acc3;
        res[4] = acc4; res[5] = acc5; res[6] = acc6; res[7] = acc7;
        #pragma unroll
        for (int k = 0; k < 8; k++) nxt[base + k] = res[k];
        __syncwarp();
        float* t_ = cur; cur = nxt; nxt = t_;
    }

    ((float4*)dst)[lane * 2]     = make_float4(res[0], res[1], res[2], res[3]);
    ((float4*)dst)[lane * 2 + 1] = make_float4(res[4], res[5], res[6], res[7]);
}

// ---------------------------------------------------------------------------
// K1: blocks [0,32) expm(ge) 8/block; [32,152) commut; [152,664) head (b,sp).
__global__ void __launch_bounds__(256) k_front(
        const float* __restrict__ ge,
        const float* __restrict__ mean, const float* __restrict__ logvar,
        const float* __restrict__ z, const float* __restrict__ lw,
        const float* __restrict__ lb, const float* __restrict__ gn,
        float* __restrict__ out) {
    __shared__ float sm[4096];
    const int tid = threadIdx.x;
    const int wid = tid >> 5;
    const int blk = blockIdx.x;

    if (blk < 32) {
        const int m = blk * 8 + wid;
        float res[8];
        warp_expm(ge + m * 256, g_syms + m * 256, 1.0f,
                  sm + wid * 512, sm + wid * 512 + 256, res);
    } else if (blk < 152) {
        // ---- commut pair j = blk-32 ----
        float* gA  = sm;
        float* gB  = sm + 256;
        float* gCa = sm + 512;
        float* gCb = sm + 768;
        float* rwp = sm + 1024;
        const int j = blk - 32;
        int p = j;
        int a = 0;
        while (p >= 15 - a) { p -= 15 - a; a++; }
        const int b2 = a + 1 + p;
        const int r = tid >> 4, s = tid & 15;

        gA[tid] = ge[a * 256 + tid];
        gB[tid] = ge[b2 * 256 + tid];
        {
            int c = tid >> 4, ss = tid & 15;
            gCa[tid] = ge[(c * 16) * 256 + a * 16 + ss];
            gCb[tid] = ge[(c * 16) * 256 + b2 * 16 + ss];
        }
        __syncthreads();

        float R1 = 0.f, R2 = 0.f;
        #pragma unroll
        for (int cc = 0; cc < 16; cc++) {
            R1 += gA[r * 16 + cc] * gCb[cc * 16 + s];
            R2 += gB[r * 16 + cc] * gCa[cc * 16 + s];
        }
        float d = R1 - R2;
        float local = d * d;
        #pragma unroll
        for (int off = 16; off > 0; off >>= 1)
            local += __shfl_down_sync(0xffffffffu, local, off);
        if ((tid & 31) == 0) rwp[tid >> 5] = local;
        __syncthreads();
        if (tid == 0) {
            float t = 0.f;
            #pragma unroll
            for (int w = 0; w < 8; w++) t += rwp[w];
            atomicAdd(&g_acc[3], (double)(2.0f * t) * (double)(120 - j));
        }
    } else {
        // ---- head: block = (b, sector-pair sp) ----
        float* feat  = sm;          // 64
        float* probl = sm + 64;     // 36 local rows
        const int idx = blk - 152;
        const int b = idx >> 3, sp = idx & 7;

        if (tid < 64) {
            float v;
            if (tid < 16)       v = mean[b * 16 + tid];
            else if (tid < 32)  v = expf(0.5f * logvar[b * 16 + (tid - 16)]);
            else if (tid < 48)  v = mean[(64 + b) * 16 + (tid - 32)];
            else                v = expf(0.5f * mean[(64 + b) * 16 + (tid - 48)]);
            feat[tid] = v;
        }
        __syncthreads();

        // 36 rows: lr<4 -> sector logits rows 4sp+lr; else fprob rows 32+32sp+(lr-4)
        {
            const int lane = tid & 31;
            const float f0 = feat[lane], f1 = feat[lane + 32];
            for (int lr = wid; lr < 36; lr += 8) {
                const int jj = (lr < 4) ? (4 * sp + lr) : (32 + 32 * sp + (lr - 4));
                const float* wrow = lw + jj * 64;
                float acc = wrow[lane] * f0 + wrow[lane + 32] * f1;
                acc += __shfl_down_sync(0xffffffffu, acc, 16);
                acc += __shfl_down_sync(0xffffffffu, acc, 8);
                acc += __shfl_down_sync(0xffffffffu, acc, 4);
                acc += __shfl_down_sync(0xffffffffu, acc, 2);
                acc += __shfl_down_sync(0xffffffffu, acc, 1);
                if (lane == 0) probl[lr] = acc + lb[jj];
            }
        }
        __syncthreads();

        if (tid < 2) {
            const int t = tid;
            const int s = 2 * sp + t;
            float l0 = probl[2 * t], l1 = probl[2 * t + 1];
            float m = fmaxf(l0, l1);
            float e0 = expf(l0 - m), e1 = expf(l1 - m);
            float Z = e0 + e1;
            float p0 = e0 / Z, p1 = e1 / Z;
            float mm = fmaxf(p0, p1);
            float lse = mm + logf(expf(p0 - mm) + expf(p1 - mm));
            float zd = z[b * 16 + s] - z[(64 + b) * 16 + s];
            int tgt = (fabsf(zd) > 0.2f) ? 1 : 0;
            float v = -((tgt ? p1 : p0) - lse);
            v += __shfl_down_sync(0x3u, v, 1);
            if (t == 0) atomicAdd(&g_acc[4], (double)v);

            float g0 = gn[(b * 16 + s) * 2], g1 = gn[(b * 16 + s) * 2 + 1];
            const float TAUF = 0.0001f;
            float d0 = (l0 + g0) / TAUF, d1 = (l1 + g1) / TAUF;
            float m2 = fmaxf(d0, d1);
            float a0 = expf(d0 - m2), a1 = expf(d1 - m2);
            float attn1 = a1 / (a0 + a1);
            out[OFF_ATT + b * 272 + s] = attn1;

            float mx = -1e30f;
            #pragma unroll
            for (int u = 0; u < 16; u++) mx = fmaxf(mx, probl[4 + 16 * t + u]);
            float ex[16];
            float sum = 0.f;
            #pragma unroll
            for (int u = 0; u < 16; u++) {
                ex[u] = expf(probl[4 + 16 * t + u] - mx);
                sum += ex[u];
            }
            float inv = 1.0f / sum;
            #pragma unroll
            for (int u = 0; u < 16; u++) {
                float f = ex[u] * inv;
                out[OFF_ATT + b * 272 + 16 + s * 16 + u] = f;
                g_w[b * 256 + s * 16 + u] = f * attn1;
            }
        }
    }
}

// ---------------------------------------------------------------------------
// K2: blocks [0,128) diff (2 group-elements per block); [128,192) subsyms.
__global__ void __launch_bounds__(256) k_mid(const float* __restrict__ z,
                                             const float* __restrict__ ge,
                                             float* __restrict__ out) {
    __shared__ float sm[2816];
    const int tid = threadIdx.x;
    const int blk = blockIdx.x;

    if (blk < 128) {
        float* sy  = sm;          // 512 (two 16x16)
        float* zsh = sm + 512;    // 2048
        float* rwp = sm + 2560;   // 8

        sy[tid] = g_syms[blk * 512 + tid];
        sy[tid + 256] = g_syms[blk * 512 + 256 + tid];
        #pragma unroll
        for (int i = 0; i < 8; i++) zsh[tid + 256 * i] = z[tid + 256 * i];
        __syncthreads();

        const int half = tid >> 7, b = tid & 127;
        const float* syp = sy + half * 256;
        float zr[16];
        #pragma unroll
        for (int d = 0; d < 16; d++) zr[d] = zsh[b * 16 + d];

        float dv[16];
        float s2 = 0.f, mx = 0.f;
        #pragma unroll
        for (int d = 0; d < 16; d++) {
            float dot0 = 0.f, dot1 = 0.f;
            #pragma unroll
            for (int k = 0; k < 16; k += 2) {
                dot0 += zr[k] * syp[k * 16 + d];
                dot1 += zr[k + 1] * syp[(k + 1) * 16 + d];
            }
            float v = zr[d] - (dot0 + dot1);
            dv[d] = v;
            float q = v * v;
            s2 += q;
            mx = fmaxf(mx, q);
        }
        float sp = s2 - mx;
        sp = sp * sp;

        #pragma unroll
        for (int off = 16; off > 0; off >>= 1)
            sp += __shfl_down_sync(0xffffffffu, sp, off);
        if ((tid & 31) == 0) rwp[tid >> 5] = sp;
        __syncthreads();
        if (tid == 0) {
            float t = 0.f;
            #pragma unroll
            for (int w = 0; w < 8; w++) t += rwp[w];
            atomicAdd(&g_acc[0], (double)t);
        }

        const float inv = rsqrtf(s2);
        float* dstu = g_u + ((blk * 2 + half) * 128 + b) * 16;
        #pragma unroll
        for (int d = 0; d < 16; d++) dstu[d] = dv[d] * inv;
    } else {
        // ---- subsyms b = blk-128 ----
        float* wsh = sm;
        const int b = blk - 128;
        wsh[tid] = g_w[b * 256 + tid];
        __syncthreads();

        float Sacc = 0.f;
        #pragma unroll 1
        for (int s = 0; s < 16; s++) {
            float a = 0.f;
            #pragma unroll
            for (int u = 0; u < 16; u++)
                a += wsh[s * 16 + u] * ge[(s * 16 + u) * 256 + tid];
            out[OFF_SUB + b * 4096 + s * 256 + tid] = a;
            Sacc += a;
        }
        g_S[b * 256 + tid] = Sacc;
    }
}

// ---------------------------------------------------------------------------
// K3: blocks [0,16) expm(+/-S) 8/block + fused tz + equivariant partials;
//     blocks [16,2312) gram tiles.
__global__ void __launch_bounds__(256) k_back(const int* __restrict__ sidx,
                                              const float* __restrict__ z,
                                              float* __restrict__ out) {
    __shared__ float sm[4352];
    const int tid = threadIdx.x;

    if (blockIdx.x < 16) {
        const int wid = tid >> 5;
        const int lane = tid & 31;
        const int m = blockIdx.x * 8 + wid;     // 0..127
        const int b = m & 63;
        const bool inv = m >= 64;
        float* dst = inv ? (g_inv + b * 256) : (out + OFF_FWD + b * 256);
        float res[8];
        warp_expm(g_S + b * 256, dst, inv ? -1.0f : 1.0f,
                  sm + wid * 512, sm + wid * 512 + 256, res);

        // ---- fused tz + equivariant partial ----
        // lane holds P[r][c0..c0+7], r = lane>>1, c0 = (lane&1)*8.
        // tz[d] = sum_r zin[r] * P[r][d]; reduce over lanes with same (lane&1).
        const int r = lane >> 1;
        const int c0 = (lane & 1) * 8;
        const int zin = inv ? (64 + b) : b;       // row multiplied into matrix
        const int zcm = inv ? b : (64 + b);       // row compared against
        const float zv = z[zin * 16 + r];
        float part[8];
        #pragma unroll
        for (int k = 0; k < 8; k++) part[k] = zv * res[k];
        #pragma unroll
        for (int off = 2; off < 32; off <<= 1) {
            #pragma unroll
            for (int k = 0; k < 8; k++)
                part[k] += __shfl_xor_sync(0xffffffffu, part[k], off);
        }
        // lanes 0 and 1 hold tz[c0..c0+7] for c0 = 0, 8
        float e = 0.f;
        if (lane < 2) {
            float* tzout = out + (inv ? OFF_TZ2 : OFF_TZ1) + b * 16 + c0;
            ((float4*)tzout)[0] = make_float4(part[0], part[1], part[2], part[3]);
            ((float4*)tzout)[1] = make_float4(part[4], part[5], part[6], part[7]);
            const float4 zc0 = *(const float4*)(z + zcm * 16 + c0);
            const float4 zc1 = *(const float4*)(z + zcm * 16 + c0 + 4);
            float d;
            d = part[0] - zc0.x; e += d * d;  d = part[1] - zc0.y; e += d * d;
            d = part[2] - zc0.z; e += d * d;  d = part[3] - zc0.w; e += d * d;
            d = part[4] - zc1.x; e += d * d;  d = part[5] - zc1.y; e += d * d;
            d = part[6] - zc1.z; e += d * d;  d = part[7] - zc1.w; e += d * d;
        }
        e += __shfl_down_sync(0xffffffffu, e, 1);
        if (lane == 0) atomicAdd(&g_acc[5], (double)e);
        return;
    }

    float* As  = sm;
    float* Bs  = sm + 2048;
    float* rwp = sm + 4096;
    const int bi = blockIdx.x - 16;
    const bool isOrth = bi >= 2176;

    const float* baseA;
    const float* baseB;
    float mult;
    if (!isOrth) {
        const int sec = bi / 136;
        int p = bi % 136;
        int ti = 0;
        while (p >= 16 - ti) { p -= 16 - ti; ti++; }
        const int tj = ti + p;
        baseA = g_u + (sec * 2048 + ti * 128) * 16;
        baseB = g_u + (sec * 2048 + tj * 128) * 16;
        mult = (ti == tj) ? 1.0f : 2.0f;
    } else {
        int p = bi - 2176;
        int s = 0;
        while (p >= 15 - s) { p -= 15 - s; s++; }
        const int t2 = s + 1 + p;
        baseA = g_u + (s * 16 + sidx[s]) * 2048;
        baseB = g_u + (t2 * 16 + sidx[t2]) * 2048;
        mult = 2.0f;
    }

    // Load both 128x16 tiles transposed to [k][m].
    {
        const float4* a4 = (const float4*)baseA;
        const float4* b4 = (const float4*)baseB;
        #pragma unroll
        for (int i = 0; i < 2; i++) {
            const int idx = tid * 2 + i;
            const float4 va = a4[idx];
            const float4 vb = b4[idx];
            const int m = idx >> 2;
            const int k = (idx & 3) * 4;
            As[(k + 0) * 128 + m] = va.x; As[(k + 1) * 128 + m] = va.y;
            As[(k + 2) * 128 + m] = va.z; As[(k + 3) * 128 + m] = va.w;
            Bs[(k + 0) * 128 + m] = vb.x; Bs[(k + 1) * 128 + m] = vb.y;
            Bs[(k + 2) * 128 + m] = vb.z; Bs[(k + 3) * 128 + m] = vb.w;
        }
    }
    __syncthreads();

    const int tx = tid & 15, ty = tid >> 4;
    unsigned long long acc[8][4];
    #pragma unroll
    for (int m = 0; m < 8; m++)
        #pragma unroll
        for (int n = 0; n < 4; n++) acc[m][n] = 0ULL;

    #pragma unroll
    for (int k = 0; k < 16; k++) {
        const float4 a0 = *(const float4*)(As + k * 128 + ty * 8);
        const float4 a1 = *(const float4*)(As + k * 128 + ty * 8 + 4);
        unsigned long long bp[4];
        {
            const ulonglong2 q0 = *(const ulonglong2*)(Bs + k * 128 + tx * 8);
            const ulonglong2 q1 = *(const ulonglong2*)(Bs + k * 128 + tx * 8 + 4);
            bp[0] = q0.x; bp[1] = q0.y; bp[2] = q1.x; bp[3] = q1.y;
        }
        const float av[8] = {a0.x, a0.y, a0.z, a0.w, a1.x, a1.y, a1.z, a1.w};
        #pragma unroll
        for (int m = 0; m < 8; m++) {
            const unsigned long long am = pk2(av[m], av[m]);
            #pragma unroll
            for (int n = 0; n < 4; n++) acc[m][n] = ffma2(am, bp[n], acc[m][n]);
        }
    }

    float local = 0.f;
    #pragma unroll
    for (int m = 0; m < 8; m++) {
        float l0, h0, l1, h1, l2, h2, l3, h3;
        upk2(l0, h0, acc[m][0]); upk2(l1, h1, acc[m][1]);
        upk2(l2, h2, acc[m][2]); upk2(l3, h3, acc[m][3]);
        if (isOrth) {
            local += l0 * l0 + h0 * h0 + l1 * l1 + h1 * h1
                   + l2 * l2 + h2 * h2 + l3 * l3 + h3 * h3;
        } else {
            // fuse 4 logs: factors >= 1e-9 so product >= 1e-36 > FLT_MIN
            float p0 = fmaf(l0, l0, 1e-9f) * fmaf(h0, h0, 1e-9f)
                     * fmaf(l1, l1, 1e-9f) * fmaf(h1, h1, 1e-9f);
            float p1 = fmaf(l2, l2, 1e-9f) * fmaf(h2, h2, 1e-9f)
                     * fmaf(l3, l3, 1e-9f) * fmaf(h3, h3, 1e-9f);
            local -= __logf(p0) + __logf(p1);
        }
    }
    local *= mult;

    #pragma unroll
    for (int off = 16; off > 0; off >>= 1)
        local += __shfl_down_sync(0xffffffffu, local, off);
    if ((tid & 31) == 0) rwp[tid >> 5] = local;
    __syncthreads();
    if (tid == 0) {
        float t = 0.f;
        #pragma unroll
        for (int w = 0; w < 8; w++) t += rwp[w];
        atomicAdd(&g_acc[isOrth ? 2 : 1], (double)t);
    }
}

// ---------------------------------------------------------------------------
// K4: scalar finalize only (reads g_acc, writes 6 scalars, resets).
__global__ void k_tail(float* __restrict__ out) {
    if (threadIdx.x == 0) {
        out[OFF_EQ]   = (float)(g_acc[5] / 1024.0);
        out[OFF_SPA]  = (float)(g_acc[0] / 32768.0);
        out[OFF_PAR]  = (float)(g_acc[1] / 67108864.0);
        out[OFF_ORTH] = (float)(g_acc[2] / 4194304.0);
        out[OFF_COM]  = (float)(g_acc[3] / 16777216.0);
        out[OFF_SEC]  = (float)(g_acc[4] / 64.0);
        #pragma unroll
        for (int i = 0; i < 8; i++) g_acc[i] = 0.0;   // ready for next replay
    }
}

// ---------------------------------------------------------------------------
extern "C" void kernel_launch(void* const* d_in, const int* in_sizes, int n_in,
                              void* d_out, int out_size) {
    const float* mean   = (const float*)d_in[0];
    const float* logvar = (const float*)d_in[1];
    const float* z      = (const float*)d_in[2];
    const float* ge     = (const float*)d_in[3];
    const float* lw     = (const float*)d_in[4];
    const float* lb     = (const float*)d_in[5];
    const float* gn     = (const float*)d_in[6];
    const int*   sidx   = (const int*)d_in[7];
    float* out = (float*)d_out;

    k_front<<<664, 256>>>(ge, mean, logvar, z, lw, lb, gn, out); // expm(ge)+commut+head
    k_mid<<<192, 256>>>(z, ge, out);                             // diff+sparse+subsyms
    k_back<<<2312, 256>>>(sidx, z, out);                         // expm(+/-S)+tz+gram
    k_tail<<<1, 32>>>(out);                                      // scalars+reset
}